// round 1
// baseline (speedup 1.0000x reference)
#include <cuda_runtime.h>

// ---------------- constants ----------------
#define FM     48
#define NPATH  11
#define NMAX   1024     // max nodes supported
#define BB     8        // batches
#define PP     2
#define DD     192      // 4*FM
#define MN_MAX 4096

// ---------------- device scratch (no allocations allowed) ----------------
__device__ float  g_CG[NPATH * 125];          // dense padded (2l1+1,2l2+1,2l3+1)
__device__ float  g_Weff0[144 * 96];          // [u*96 + f*2 + o]
__device__ float  g_Weff1[192 * 48];          // [u*48 + f]
__device__ float  g_Weff2[192 * 48];
__device__ float4 g_M4[NMAX * 48 * 4];        // per node, per f: 4 rows of float4
__device__ int    g_nodeAt[BB * MN_MAX];      // (b,pos) -> node or -1

// path tables
__constant__ int c_l1[NPATH]   = {0,0,0,1,1,1,1,2,2,2,2};
__constant__ int c_l2[NPATH]   = {0,1,2,0,1,1,2,0,1,2,2};
__constant__ int c_l3[NPATH]   = {0,1,2,1,0,2,1,2,1,0,2};
__constant__ int c_slot[NPATH] = {0,0,0,48,48,48,96,96,144,96,144};

// ---------------- CG computation (fp64 port of reference) ----------------
struct cplx { double re, im; };
__device__ __forceinline__ cplx cmul(cplx a, cplx b){ return {a.re*b.re - a.im*b.im, a.re*b.im + a.im*b.re}; }
__device__ __forceinline__ cplx cconj(cplx a){ return {a.re, -a.im}; }

__device__ double d_fact(int x){ double r = 1.0; for (int i = 2; i <= x; i++) r *= (double)i; return r; }

__device__ double su2_cg(int j1,int j2,int j3,int m1,int m2,int m3){
    if (m1 + m2 != m3) return 0.0;
    double pre = sqrt((double)(2*j3+1) * d_fact(j3+j1-j2) * d_fact(j3-j1+j2) * d_fact(j1+j2-j3)
                      / d_fact(j1+j2+j3+1));
    pre *= sqrt(d_fact(j3+m3)*d_fact(j3-m3)*d_fact(j1-m1)*d_fact(j1+m1)*d_fact(j2-m2)*d_fact(j2+m2));
    double s = 0.0;
    for (int v = 0; v <= j1 + j2 - j3; v++){
        int a1 = j1+j2-j3-v, a2 = j1-m1-v, a3 = j2+m2-v, a4 = j3-j2+m1+v, a5 = j3-j1-m2+v;
        if (a1 < 0 || a2 < 0 || a3 < 0 || a4 < 0 || a5 < 0) continue;
        double den = d_fact(v)*d_fact(a1)*d_fact(a2)*d_fact(a3)*d_fact(a4)*d_fact(a5);
        s += ((v & 1) ? -1.0 : 1.0) / den;
    }
    return pre * s;
}

__device__ void u_fill(int l, cplx* U){
    int n = 2*l + 1;
    for (int i = 0; i < n*n; i++) U[i] = {0.0, 0.0};
    double s2 = sqrt(0.5);
    for (int m = -l; m <= l; m++){
        int a = l + m;
        if (m > 0){
            U[a*n + (l+m)] = {((m & 1) ? -1.0 : 1.0) * s2, 0.0};
            U[a*n + (l-m)] = {s2, 0.0};
        } else if (m == 0){
            U[a*n + l] = {1.0, 0.0};
        } else {
            int mm = -m;
            U[a*n + (l+m)] = {0.0, s2};
            U[a*n + (l-m)] = {0.0, -(((mm & 1) ? -1.0 : 1.0)) * s2};
        }
    }
}

__global__ void k_cg(){
    int p = blockIdx.x, tid = threadIdx.x;
    int l1 = c_l1[p], l2 = c_l2[p], l3 = c_l3[p];
    int n1 = 2*l1+1, n2 = 2*l2+1, n3 = 2*l3+1, tot = n1*n2*n3;
    __shared__ double sCc[125];
    __shared__ cplx   sU1[25], sU2[25], sU3[25];
    __shared__ double sRe[125], sIm[125];

    for (int i = tid; i < tot; i += blockDim.x){
        int a = i / (n2*n3), b = (i / n3) % n2, c = i % n3;
        sCc[i] = su2_cg(l1, l2, l3, a - l1, b - l2, c - l3);
    }
    if (tid == 0){ u_fill(l1, sU1); u_fill(l2, sU2); u_fill(l3, sU3); }
    __syncthreads();

    for (int i = tid; i < tot; i += blockDim.x){
        int a = i / (n2*n3), b = (i / n3) % n2, c = i % n3;
        double re = 0, im = 0;
        for (int q1 = 0; q1 < n1; q1++)
        for (int q2 = 0; q2 < n2; q2++){
            cplx u12 = cmul(cconj(sU1[a*n1 + q1]), cconj(sU2[b*n2 + q2]));
            if (u12.re == 0.0 && u12.im == 0.0) continue;
            for (int q3 = 0; q3 < n3; q3++){
                double cc = sCc[q1*n2*n3 + q2*n3 + q3];
                if (cc == 0.0) continue;
                cplx t = cmul(u12, sU3[c*n3 + q3]);
                re += t.re * cc; im += t.im * cc;
            }
        }
        sRe[i] = re; sIm[i] = im;
    }
    __syncthreads();

    if (tid == 0){
        double mr = 0, mi = 0;
        for (int i = 0; i < tot; i++){ mr = fmax(mr, fabs(sRe[i])); mi = fmax(mi, fabs(sIm[i])); }
        const double* src = (mi > mr) ? sIm : sRe;
        double nrm = 0; for (int i = 0; i < tot; i++) nrm += src[i]*src[i];
        nrm = sqrt(nrm); if (nrm < 1e-12) nrm = 1e-12;
        for (int i = 0; i < 125; i++)
            g_CG[p*125 + i] = (i < tot) ? (float)(src[i] / nrm) : 0.f;
    }
}

// ---------------- fold W_out with Wt ----------------
__global__ void k_weff(const float* __restrict__ Wo0, const float* __restrict__ Wo1,
                       const float* __restrict__ Wo2, const float* __restrict__ Wt0,
                       const float* __restrict__ Wt1, const float* __restrict__ Wt2){
    int idx = blockIdx.x * blockDim.x + threadIdx.x;
    const float s0  = rsqrtf(144.f * 16.f);   // (3Fm)^-1/2 * K^-1/2
    const float s12 = rsqrtf(192.f * 16.f);
    if (idx < 144*96){
        int u = idx / 96, r = idx % 96, f = r >> 1, o = r & 1;
        float acc = 0.f;
        #pragma unroll
        for (int k = 0; k < 16; k++) acc += Wo0[u*768 + k*48 + f] * Wt0[k*2 + o];
        g_Weff0[idx] = acc * s0;
    } else if (idx < 144*96 + 192*48){
        int j = idx - 144*96, u = j / 48, f = j % 48;
        float acc = 0.f;
        #pragma unroll
        for (int k = 0; k < 16; k++) acc += Wo1[u*768 + k*48 + f] * Wt1[k];
        g_Weff1[j] = acc * s12;
    } else if (idx < 144*96 + 2*192*48){
        int j = idx - 144*96 - 192*48, u = j / 48, f = j % 48;
        float acc = 0.f;
        #pragma unroll
        for (int k = 0; k < 16; k++) acc += Wo2[u*768 + k*48 + f] * Wt2[k];
        g_Weff2[j] = acc * s12;
    }
}

// ---------------- batch -> (b,pos) slot map ----------------
__global__ void k_setup(const int* __restrict__ batch, int n, int MN){
    __shared__ int cnt[BB], starts[BB];
    int tid = threadIdx.x;
    if (tid < BB) cnt[tid] = 0;
    __syncthreads();
    for (int i = tid; i < n; i += blockDim.x) atomicAdd(&cnt[batch[i]], 1);
    __syncthreads();
    if (tid == 0){ int s = 0; for (int b = 0; b < BB; b++){ starts[b] = s; s += cnt[b]; } }
    __syncthreads();
    for (int i = tid; i < BB*MN; i += blockDim.x) g_nodeAt[i] = -1;
    __syncthreads();
    for (int i = tid; i < n; i += blockDim.x){
        int b = batch[i];
        int pos = i - starts[b];
        if (pos < MN) g_nodeAt[b*MN + pos] = i;
    }
}

// ---------------- per-node equivariant compute ----------------
__global__ void __launch_bounds__(128) k_node(const float* __restrict__ nf,
                                              const float* __restrict__ W0,
                                              const float* __restrict__ W1,
                                              const float* __restrict__ W2,
                                              const float* __restrict__ tpw){
    int node = blockIdx.x, tid = threadIdx.x;
    __shared__ float s_x[9*48], s_y[9*48], s_w[2304], s_a[5*48];
    __shared__ float s_o0[144], s_o1[3*192], s_o2[5*192];
    __shared__ float s_g0[96], s_g1[3*48], s_g2[5*48];

    const float sF = rsqrtf(48.f);
    const float* row = nf + (size_t)node * 432;

    // load x into [component][u]
    for (int i = tid; i < 432; i += 128){
        int c = i / 48, u = i % 48;
        float v;
        if (c == 0)      v = row[u];
        else if (c < 4)  v = row[48  + u*3 + (c-1)];
        else             v = row[192 + u*5 + (c-4)];
        s_x[c*48 + u] = v;
    }
    __syncthreads();

    // y = (x @ W_lin) * sF
    for (int i = tid; i < 432; i += 128){
        int c = i / 48, v = i % 48;
        const float* W = (c == 0) ? W0 : (c < 4) ? W1 : W2;
        float acc = 0.f;
        #pragma unroll
        for (int u = 0; u < 48; u++) acc += s_x[c*48 + u] * W[u*48 + v];
        s_y[i] = acc * sF;
    }
    __syncthreads();

    // tensor-product paths
    for (int p = 0; p < NPATH; p++){
        int l1 = c_l1[p], l2 = c_l2[p], l3 = c_l3[p];
        int n1 = 2*l1+1, n2 = 2*l2+1, n3 = 2*l3+1;
        int cb1 = (l1 == 0) ? 0 : (l1 == 1) ? 1 : 4;
        int cb2 = (l2 == 0) ? 0 : (l2 == 1) ? 1 : 4;

        for (int i = tid; i < 2304; i += 128) s_w[i] = tpw[p*2304 + i];
        __syncthreads();

        for (int i = tid; i < n2*48; i += 128){
            int k = i / 48, u = i % 48;
            float acc = 0.f;
            #pragma unroll
            for (int v = 0; v < 48; v++) acc += s_w[u*48 + v] * s_y[(cb2 + k)*48 + v];
            s_a[i] = acc * sF;
        }
        __syncthreads();

        const float* cg = g_CG + p*125;
        for (int i = tid; i < n3*48; i += 128){
            int c = i / 48, u = i % 48;
            float acc = 0.f;
            for (int m = 0; m < n1; m++){
                float ym = s_y[(cb1 + m)*48 + u];
                for (int k = 0; k < n2; k++){
                    float cgv = cg[m*n2*n3 + k*n3 + c];
                    acc += ym * s_a[k*48 + u] * cgv;
                }
            }
            int so = c_slot[p];
            if (l3 == 0)      s_o0[so + u]          = acc;
            else if (l3 == 1) s_o1[c*192 + so + u]  = acc;
            else              s_o2[c*192 + so + u]  = acc;
        }
        __syncthreads();
    }

    // g = o @ Weff
    for (int i = tid; i < 480; i += 128){
        if (i < 96){
            float acc = 0.f;
            #pragma unroll 4
            for (int u = 0; u < 144; u++) acc += s_o0[u] * g_Weff0[u*96 + i];
            s_g0[i] = acc;
        } else if (i < 240){
            int j = i - 96, ii = j / 48, f = j % 48;
            float acc = 0.f;
            #pragma unroll 4
            for (int u = 0; u < 192; u++) acc += s_o1[ii*192 + u] * g_Weff1[u*48 + f];
            s_g1[j] = acc;
        } else {
            int j = i - 240, ii = j / 48, f = j % 48;
            float acc = 0.f;
            #pragma unroll 4
            for (int u = 0; u < 192; u++) acc += s_o2[ii*192 + u] * g_Weff2[u*48 + f];
            s_g2[j] = acc;
        }
    }
    __syncthreads();

    // assemble 4x4 M per f and store
    if (tid < 48){
        int f = tid;
        float a0 = s_g0[f*2 + 0], a1 = s_g0[f*2 + 1];
        float v0 = s_g1[f], v1 = s_g1[48 + f], v2 = s_g1[96 + f];
        float dd[5];
        #pragma unroll
        for (int m = 0; m < 5; m++) dd[m] = s_g2[m*48 + f];
        const float* cg112 = g_CG + 5*125;   // path 5 is (1,1,2), dims (3,3,5)
        const float is3 = 0.57735026918962576f;
        float S[3][3];
        #pragma unroll
        for (int i = 0; i < 3; i++)
        #pragma unroll
        for (int j = 0; j < 3; j++){
            float acc = (i == j) ? a1 * is3 : 0.f;
            #pragma unroll
            for (int m = 0; m < 5; m++) acc += dd[m] * cg112[i*15 + j*5 + m];
            S[i][j] = acc;
        }
        float4* out = g_M4 + ((size_t)node*48 + f)*4;
        out[0] = make_float4(a0, v0,      v1,      v2);
        out[1] = make_float4(v0, S[0][0], S[0][1], S[0][2]);
        out[2] = make_float4(v1, S[1][0], S[1][1], S[1][2]);
        out[3] = make_float4(v2, S[2][0], S[2][1], S[2][2]);
    }
}

// ---------------- single-pass output fill (the 302MB store) ----------------
__global__ void k_fill(float4* __restrict__ out, long long total4, int MN){
    long long idx = (long long)blockIdx.x * blockDim.x + threadIdx.x;
    if (idx >= total4) return;
    int col4 = (int)(idx % 48);
    long long t = idx / 48;
    int row = (int)(t % 192); t /= 192;
    t >>= 1;                               // P dimension: identical slices
    int pos = (int)(t % MN);
    int b   = (int)(t / MN);
    int n = g_nodeAt[b*MN + pos];
    float4 v = make_float4(0.f, 0.f, 0.f, 0.f);
    int f = row >> 2;
    if (n >= 0 && col4 == f)
        v = g_M4[((size_t)n*48 + f)*4 + (row & 3)];
    out[idx] = v;
}

// ---------------- launch ----------------
extern "C" void kernel_launch(void* const* d_in, const int* in_sizes, int n_in,
                              void* d_out, int out_size){
    const float* node_feats = (const float*)d_in[0];
    const float* W_lin0     = (const float*)d_in[1];
    const float* W_lin1     = (const float*)d_in[2];
    const float* W_lin2     = (const float*)d_in[3];
    const float* tp_w       = (const float*)d_in[4];
    const float* W_out0     = (const float*)d_in[5];
    const float* W_out1     = (const float*)d_in[6];
    const float* W_out2     = (const float*)d_in[7];
    const float* Wt0        = (const float*)d_in[8];
    const float* Wt1        = (const float*)d_in[9];
    const float* Wt2        = (const float*)d_in[10];
    const int*   batch      = (const int*)  d_in[11];

    int n  = in_sizes[0] / 432;                       // nodes
    int MN = out_size / (BB * PP * DD * DD);          // max_nodes
    long long total4 = (long long)out_size / 4;

    k_cg<<<NPATH, 128>>>();
    k_weff<<<(144*96 + 2*192*48 + 255)/256, 256>>>(W_out0, W_out1, W_out2, Wt0, Wt1, Wt2);
    k_setup<<<1, 512>>>(batch, n, MN);
    k_node<<<n, 128>>>(node_feats, W_lin0, W_lin1, W_lin2, tp_w);
    k_fill<<<(unsigned)((total4 + 255)/256), 256>>>((float4*)d_out, total4, MN);
}

// round 2
// speedup vs baseline: 2.1654x; 2.1654x over previous
#include <cuda_runtime.h>

// ---------------- constants ----------------
#define FM     48
#define NPATH  11
#define NMAX   1024
#define BB     8
#define PP     2
#define DD     192
#define MN_MAX 4096

// ---------------- device scratch ----------------
__device__ float  g_CG[NPATH * 125];
__device__ float  g_Weff0[144 * 96];
__device__ float  g_Weff1[192 * 48];
__device__ float  g_Weff2[192 * 48];
__device__ float  g_tpwT[NPATH * 2304];       // [p][v*48+u]
__device__ float  g_y[NMAX * 9 * 48];         // [n][c*48+v]
__device__ float  g_a[NMAX * 35 * 48];        // [n][j*48+u]
__device__ float  g_o[NMAX * 1680];           // [n][ o0:0..144 | o1:144..720 | o2:720..1680 ]
__device__ float  g_g[NMAX * 480];            // [n][ g0:0..96 | g1:96..240 | g2:240..480 ]
__device__ float4 g_M4[NMAX * 48 * 4];
__device__ int    g_nodeAt[BB * MN_MAX];

// path tables
__constant__ int c_l1[NPATH]   = {0,0,0,1,1,1,1,2,2,2,2};
__constant__ int c_l2[NPATH]   = {0,1,2,0,1,1,2,0,1,2,2};
__constant__ int c_l3[NPATH]   = {0,1,2,1,0,2,1,2,1,0,2};
__constant__ int c_aoff[NPATH] = {0,1,4,9,10,13,16,21,22,25,30};

// K2 (a) tables: 35 rows = per-path k slots
__constant__ int c_j_p[35]  = {0, 1,1,1, 2,2,2,2,2, 3, 4,4,4, 5,5,5, 6,6,6,6,6, 7, 8,8,8, 9,9,9,9,9, 10,10,10,10,10};
__constant__ int c_j_c2[35] = {0, 1,2,3, 4,5,6,7,8, 0, 1,2,3, 1,2,3, 4,5,6,7,8, 0, 1,2,3, 4,5,6,7,8, 4,5,6,7,8};

// K3 (o) tables: 35 rows = per-path c3 outputs
__constant__ int c_os_p[35]  = {0, 1,1,1, 2,2,2,2,2, 3,3,3, 4, 5,5,5,5,5, 6,6,6, 7,7,7,7,7, 8,8,8, 9, 10,10,10,10,10};
__constant__ int c_os_c3[35] = {0, 0,1,2, 0,1,2,3,4, 0,1,2, 0, 0,1,2,3,4, 0,1,2, 0,1,2,3,4, 0,1,2, 0, 0,1,2,3,4};
__constant__ int c_os_dst[35]= {0, 144,336,528, 720,912,1104,1296,1488, 192,384,576, 48,
                                768,960,1152,1344,1536, 240,432,624, 816,1008,1200,1392,1584,
                                288,480,672, 96, 864,1056,1248,1440,1632};

// ---------------- CG computation (fp32: factorials <= 5040, exact) ----------------
struct cplxf { float re, im; };
__device__ __forceinline__ cplxf cmulf(cplxf a, cplxf b){ return {a.re*b.re - a.im*b.im, a.re*b.im + a.im*b.re}; }
__device__ __forceinline__ cplxf cconjf(cplxf a){ return {a.re, -a.im}; }
__device__ float f_fact(int x){ float r = 1.f; for (int i = 2; i <= x; i++) r *= (float)i; return r; }

__device__ float su2_cgf(int j1,int j2,int j3,int m1,int m2,int m3){
    if (m1 + m2 != m3) return 0.f;
    float pre = sqrtf((float)(2*j3+1) * f_fact(j3+j1-j2) * f_fact(j3-j1+j2) * f_fact(j1+j2-j3)
                      / f_fact(j1+j2+j3+1));
    pre *= sqrtf(f_fact(j3+m3)*f_fact(j3-m3)*f_fact(j1-m1)*f_fact(j1+m1)*f_fact(j2-m2)*f_fact(j2+m2));
    float s = 0.f;
    for (int v = 0; v <= j1 + j2 - j3; v++){
        int a1 = j1+j2-j3-v, a2 = j1-m1-v, a3 = j2+m2-v, a4 = j3-j2+m1+v, a5 = j3-j1-m2+v;
        if (a1 < 0 || a2 < 0 || a3 < 0 || a4 < 0 || a5 < 0) continue;
        float den = f_fact(v)*f_fact(a1)*f_fact(a2)*f_fact(a3)*f_fact(a4)*f_fact(a5);
        s += ((v & 1) ? -1.f : 1.f) / den;
    }
    return pre * s;
}

__device__ void u_fillf(int l, cplxf* U){
    int n = 2*l + 1;
    for (int i = 0; i < n*n; i++) U[i] = {0.f, 0.f};
    float s2 = sqrtf(0.5f);
    for (int m = -l; m <= l; m++){
        int a = l + m;
        if (m > 0){
            U[a*n + (l+m)] = {((m & 1) ? -1.f : 1.f) * s2, 0.f};
            U[a*n + (l-m)] = {s2, 0.f};
        } else if (m == 0){
            U[a*n + l] = {1.f, 0.f};
        } else {
            int mm = -m;
            U[a*n + (l+m)] = {0.f, s2};
            U[a*n + (l-m)] = {0.f, -(((mm & 1) ? -1.f : 1.f)) * s2};
        }
    }
}

__global__ void k_cg(){
    int p = blockIdx.x, tid = threadIdx.x;
    int l1 = c_l1[p], l2 = c_l2[p], l3 = c_l3[p];
    int n1 = 2*l1+1, n2 = 2*l2+1, n3 = 2*l3+1, tot = n1*n2*n3;
    __shared__ float sCc[125];
    __shared__ cplxf sU1[25], sU2[25], sU3[25];
    __shared__ float sRe[125], sIm[125];
    __shared__ float sRed[128];

    for (int i = tid; i < tot; i += blockDim.x){
        int a = i / (n2*n3), b = (i / n3) % n2, c = i % n3;
        sCc[i] = su2_cgf(l1, l2, l3, a - l1, b - l2, c - l3);
    }
    if (tid == 0){ u_fillf(l1, sU1); u_fillf(l2, sU2); u_fillf(l3, sU3); }
    __syncthreads();

    for (int i = tid; i < tot; i += blockDim.x){
        int a = i / (n2*n3), b = (i / n3) % n2, c = i % n3;
        float re = 0, im = 0;
        for (int q1 = 0; q1 < n1; q1++)
        for (int q2 = 0; q2 < n2; q2++){
            cplxf u12 = cmulf(cconjf(sU1[a*n1 + q1]), cconjf(sU2[b*n2 + q2]));
            if (u12.re == 0.f && u12.im == 0.f) continue;
            for (int q3 = 0; q3 < n3; q3++){
                float cc = sCc[q1*n2*n3 + q2*n3 + q3];
                if (cc == 0.f) continue;
                cplxf t = cmulf(u12, sU3[c*n3 + q3]);
                re += t.re * cc; im += t.im * cc;
            }
        }
        sRe[i] = re; sIm[i] = im;
    }
    __syncthreads();

    // parallel max reductions
    float mr = 0.f, mi = 0.f;
    if (tid < tot){ mr = fabsf(sRe[tid]); mi = fabsf(sIm[tid]); }
    sRed[tid] = mr; __syncthreads();
    for (int s = 64; s > 0; s >>= 1){ if (tid < s) sRed[tid] = fmaxf(sRed[tid], sRed[tid+s]); __syncthreads(); }
    float maxr = sRed[0]; __syncthreads();
    sRed[tid] = mi; __syncthreads();
    for (int s = 64; s > 0; s >>= 1){ if (tid < s) sRed[tid] = fmaxf(sRed[tid], sRed[tid+s]); __syncthreads(); }
    float maxi = sRed[0]; __syncthreads();

    const float* src = (maxi > maxr) ? sIm : sRe;
    float v = (tid < tot) ? src[tid] : 0.f;
    sRed[tid] = v * v; __syncthreads();
    for (int s = 64; s > 0; s >>= 1){ if (tid < s) sRed[tid] += sRed[tid+s]; __syncthreads(); }
    float nrm = sqrtf(sRed[0]); if (nrm < 1e-12f) nrm = 1e-12f;
    if (tid < 125) g_CG[p*125 + tid] = (tid < tot) ? (v / nrm) : 0.f;
}

// ---------------- fold W_out with Wt + transpose tp_w ----------------
__global__ void k_weff(const float* __restrict__ Wo0, const float* __restrict__ Wo1,
                       const float* __restrict__ Wo2, const float* __restrict__ Wt0,
                       const float* __restrict__ Wt1, const float* __restrict__ Wt2,
                       const float* __restrict__ tpw){
    int idx = blockIdx.x * blockDim.x + threadIdx.x;
    const float s0  = rsqrtf(144.f * 16.f);
    const float s12 = rsqrtf(192.f * 16.f);
    if (idx < 13824){
        int u = idx / 96, r = idx % 96, f = r >> 1, o = r & 1;
        float acc = 0.f;
        #pragma unroll
        for (int k = 0; k < 16; k++) acc += Wo0[u*768 + k*48 + f] * Wt0[k*2 + o];
        g_Weff0[idx] = acc * s0;
    } else if (idx < 23040){
        int j = idx - 13824, u = j / 48, f = j % 48;
        float acc = 0.f;
        #pragma unroll
        for (int k = 0; k < 16; k++) acc += Wo1[u*768 + k*48 + f] * Wt1[k];
        g_Weff1[j] = acc * s12;
    } else if (idx < 32256){
        int j = idx - 23040, u = j / 48, f = j % 48;
        float acc = 0.f;
        #pragma unroll
        for (int k = 0; k < 16; k++) acc += Wo2[u*768 + k*48 + f] * Wt2[k];
        g_Weff2[j] = acc * s12;
    } else if (idx < 57600){
        int j = idx - 32256, p = j / 2304, r = j % 2304, v = r / 48, u = r % 48;
        g_tpwT[p*2304 + v*48 + u] = tpw[p*2304 + u*48 + v];
    }
}

// ---------------- batch -> slot map ----------------
__global__ void k_setup(const int* __restrict__ batch, int n, int MN){
    __shared__ int cnt[BB], starts[BB];
    int tid = threadIdx.x;
    if (tid < BB) cnt[tid] = 0;
    __syncthreads();
    for (int i = tid; i < n; i += blockDim.x) atomicAdd(&cnt[batch[i]], 1);
    __syncthreads();
    if (tid == 0){ int s = 0; for (int b = 0; b < BB; b++){ starts[b] = s; s += cnt[b]; } }
    __syncthreads();
    for (int i = tid; i < BB*MN; i += blockDim.x) g_nodeAt[i] = -1;
    __syncthreads();
    for (int i = tid; i < n; i += blockDim.x){
        int b = batch[i];
        int pos = i - starts[b];
        if (pos < MN) g_nodeAt[b*MN + pos] = i;
    }
}

// ---------------- K1: y = (x @ W_lin) * sF ----------------
__global__ void k_y(const float* __restrict__ nf, const float* __restrict__ W0,
                    const float* __restrict__ W1, const float* __restrict__ W2, int n){
    int idx = blockIdx.x * blockDim.x + threadIdx.x;
    if (idx >= n * 432) return;
    int v = idx % 48, c = (idx / 48) % 9, node = idx / 432;
    const float* row = nf + (size_t)node * 432;
    const float sF = rsqrtf(48.f);
    float acc = 0.f;
    if (c == 0){
        #pragma unroll
        for (int u = 0; u < 48; u++) acc += __ldg(row + u) * __ldg(W0 + u*48 + v);
    } else if (c < 4){
        const int i = c - 1;
        #pragma unroll
        for (int u = 0; u < 48; u++) acc += __ldg(row + 48 + u*3 + i) * __ldg(W1 + u*48 + v);
    } else {
        const int i = c - 4;
        #pragma unroll
        for (int u = 0; u < 48; u++) acc += __ldg(row + 192 + u*5 + i) * __ldg(W2 + u*48 + v);
    }
    g_y[node*432 + c*48 + v] = acc * sF;
}

// ---------------- K2: a[j] = (tpw[p] @ y[c2]) * sF ----------------
__global__ void k_a(int n){
    int idx = blockIdx.x * blockDim.x + threadIdx.x;
    if (idx >= n * 1680) return;
    int u = idx % 48, j = (idx / 48) % 35, node = idx / 1680;
    int p = c_j_p[j], c2 = c_j_c2[j];
    const float sF = rsqrtf(48.f);
    const float* yrow = g_y + node*432 + c2*48;
    const float* wT = g_tpwT + p*2304;
    float acc = 0.f;
    #pragma unroll
    for (int v = 0; v < 48; v++) acc += yrow[v] * wT[v*48 + u];
    g_a[node*1680 + j*48 + u] = acc * sF;
}

// ---------------- K3: CG contraction -> o ----------------
__global__ void k_o(int n){
    int idx = blockIdx.x * blockDim.x + threadIdx.x;
    if (idx >= n * 1680) return;
    int u = idx % 48, os = (idx / 48) % 35, node = idx / 1680;
    int p = c_os_p[os], c3 = c_os_c3[os];
    int l1 = c_l1[p], l2 = c_l2[p], l3 = c_l3[p];
    int n1 = 2*l1+1, n2 = 2*l2+1, n3 = 2*l3+1;
    int cb1 = (l1 == 0) ? 0 : (l1 == 1) ? 1 : 4;
    int ao = c_aoff[p];
    const float* cg = g_CG + p*125 + c3;
    const float* ya = g_y + node*432;
    const float* aa = g_a + node*1680;
    float acc = 0.f;
    for (int m = 0; m < n1; m++){
        float ym = ya[(cb1 + m)*48 + u];
        for (int k = 0; k < n2; k++)
            acc += ym * aa[(ao + k)*48 + u] * cg[(m*n2 + k)*n3];
    }
    g_o[node*1680 + c_os_dst[os] + u] = acc;
}

// ---------------- K4: g = o @ Weff ----------------
__global__ void k_g(int n){
    int idx = blockIdx.x * blockDim.x + threadIdx.x;
    if (idx >= n * 480) return;
    int i = idx % 480, node = idx / 480;
    const float* onode = g_o + node*1680;
    float acc = 0.f;
    if (i < 96){
        #pragma unroll 4
        for (int u = 0; u < 144; u++) acc += onode[u] * g_Weff0[u*96 + i];
    } else if (i < 240){
        int j = i - 96, ii = j / 48, f = j % 48;
        const float* ob = onode + 144 + ii*192;
        #pragma unroll 4
        for (int u = 0; u < 192; u++) acc += ob[u] * g_Weff1[u*48 + f];
    } else {
        int j = i - 240, ii = j / 48, f = j % 48;
        const float* ob = onode + 720 + ii*192;
        #pragma unroll 4
        for (int u = 0; u < 192; u++) acc += ob[u] * g_Weff2[u*48 + f];
    }
    g_g[node*480 + i] = acc;
}

// ---------------- K5: assemble 4x4 M per (node, f) ----------------
__global__ void k_m(int n){
    int idx = blockIdx.x * blockDim.x + threadIdx.x;
    if (idx >= n * 48) return;
    int f = idx % 48, node = idx / 48;
    const float* g = g_g + node*480;
    float a0 = g[f*2 + 0], a1 = g[f*2 + 1];
    float v0 = g[96 + f], v1 = g[144 + f], v2 = g[192 + f];
    float dd[5];
    #pragma unroll
    for (int m = 0; m < 5; m++) dd[m] = g[240 + m*48 + f];
    const float* cg112 = g_CG + 5*125;   // path 5 = (1,1,2), dims (3,3,5)
    const float is3 = 0.57735026918962576f;
    float S[3][3];
    #pragma unroll
    for (int i = 0; i < 3; i++)
    #pragma unroll
    for (int j = 0; j < 3; j++){
        float acc = (i == j) ? a1 * is3 : 0.f;
        #pragma unroll
        for (int m = 0; m < 5; m++) acc += dd[m] * cg112[i*15 + j*5 + m];
        S[i][j] = acc;
    }
    float4* out = g_M4 + ((size_t)node*48 + f)*4;
    out[0] = make_float4(a0, v0,      v1,      v2);
    out[1] = make_float4(v0, S[0][0], S[0][1], S[0][2]);
    out[2] = make_float4(v1, S[1][0], S[1][1], S[1][2]);
    out[3] = make_float4(v2, S[2][0], S[2][1], S[2][2]);
}

// ---------------- output fill (302MB, 32-bit index math) ----------------
__global__ void k_fill(float4* __restrict__ out, unsigned total4){
    unsigned idx = blockIdx.x * blockDim.x + threadIdx.x;
    if (idx >= total4) return;
    unsigned col4 = idx % 48u;
    unsigned t = idx / 48u;
    unsigned row = t % 192u;
    t = (t / 192u) >> 1;                 // strip P -> t = b*MN + pos
    int nd = g_nodeAt[t];
    float4 v = make_float4(0.f, 0.f, 0.f, 0.f);
    unsigned f = row >> 2;
    if (nd >= 0 && col4 == f)
        v = g_M4[((size_t)nd*48 + f)*4 + (row & 3u)];
    out[idx] = v;
}

// ---------------- launch ----------------
extern "C" void kernel_launch(void* const* d_in, const int* in_sizes, int n_in,
                              void* d_out, int out_size){
    const float* node_feats = (const float*)d_in[0];
    const float* W_lin0     = (const float*)d_in[1];
    const float* W_lin1     = (const float*)d_in[2];
    const float* W_lin2     = (const float*)d_in[3];
    const float* tp_w       = (const float*)d_in[4];
    const float* W_out0     = (const float*)d_in[5];
    const float* W_out1     = (const float*)d_in[6];
    const float* W_out2     = (const float*)d_in[7];
    const float* Wt0        = (const float*)d_in[8];
    const float* Wt1        = (const float*)d_in[9];
    const float* Wt2        = (const float*)d_in[10];
    const int*   batch      = (const int*)  d_in[11];

    int n  = in_sizes[0] / 432;
    int MN = out_size / (BB * PP * DD * DD);
    unsigned total4 = (unsigned)(out_size / 4);

    k_cg<<<NPATH, 128>>>();
    k_weff<<<(57600 + 255)/256, 256>>>(W_out0, W_out1, W_out2, Wt0, Wt1, Wt2, tp_w);
    k_setup<<<1, 512>>>(batch, n, MN);
    k_y<<<(n*432 + 255)/256, 256>>>(node_feats, W_lin0, W_lin1, W_lin2, n);
    k_a<<<(n*1680 + 255)/256, 256>>>(n);
    k_o<<<(n*1680 + 255)/256, 256>>>(n);
    k_g<<<(n*480 + 255)/256, 256>>>(n);
    k_m<<<(n*48 + 127)/128, 128>>>(n);
    k_fill<<<(total4 + 255)/256, 256>>>((float4*)d_out, total4);
}

// round 3
// speedup vs baseline: 2.7380x; 1.2644x over previous
#include <cuda_runtime.h>

// ---------------- constants ----------------
#define FM     48
#define NPATH  11
#define NMAX   1024
#define BB     8
#define PP     2
#define DD     192
#define MN_MAX 4096

// ---------------- device scratch ----------------
__device__ float  g_CG[NPATH * 125];
__device__ float  g_Weff0[144 * 96];
__device__ float  g_Weff1[192 * 48];
__device__ float  g_Weff2[192 * 48];
__device__ float  g_tpwT[NPATH * 2304];       // [p][v*48+u]
__device__ float4 g_M4[NMAX * 48 * 4];
__device__ int    g_nodeAt[BB * MN_MAX];

// path tables
__constant__ int c_l1[NPATH]   = {0,0,0,1,1,1,1,2,2,2,2};
__constant__ int c_l2[NPATH]   = {0,1,2,0,1,1,2,0,1,2,2};
__constant__ int c_l3[NPATH]   = {0,1,2,1,0,2,1,2,1,0,2};
__constant__ int c_aoff[NPATH] = {0,1,4,9,10,13,16,21,22,25,30};

// a-stage tables: 35 (path,k) slots
__constant__ int c_j_p[35]  = {0, 1,1,1, 2,2,2,2,2, 3, 4,4,4, 5,5,5, 6,6,6,6,6, 7, 8,8,8, 9,9,9,9,9, 10,10,10,10,10};
__constant__ int c_j_c2[35] = {0, 1,2,3, 4,5,6,7,8, 0, 1,2,3, 1,2,3, 4,5,6,7,8, 0, 1,2,3, 4,5,6,7,8, 4,5,6,7,8};

// o-stage tables: 35 (path,c3) outputs; dst = offset in packed o[1680]
__constant__ int c_os_p[35]  = {0, 1,1,1, 2,2,2,2,2, 3,3,3, 4, 5,5,5,5,5, 6,6,6, 7,7,7,7,7, 8,8,8, 9, 10,10,10,10,10};
__constant__ int c_os_c3[35] = {0, 0,1,2, 0,1,2,3,4, 0,1,2, 0, 0,1,2,3,4, 0,1,2, 0,1,2,3,4, 0,1,2, 0, 0,1,2,3,4};
__constant__ int c_os_dst[35]= {0, 144,336,528, 720,912,1104,1296,1488, 192,384,576, 48,
                                768,960,1152,1344,1536, 240,432,624, 816,1008,1200,1392,1584,
                                288,480,672, 96, 864,1056,1248,1440,1632};

// ---------------- CG helpers (fp32, factorials <= 5040 exact) ----------------
struct cplxf { float re, im; };
__device__ __forceinline__ cplxf cmulf(cplxf a, cplxf b){ return {a.re*b.re - a.im*b.im, a.re*b.im + a.im*b.re}; }
__device__ __forceinline__ cplxf cconjf(cplxf a){ return {a.re, -a.im}; }
__device__ float f_fact(int x){ float r = 1.f; for (int i = 2; i <= x; i++) r *= (float)i; return r; }

__device__ float su2_cgf(int j1,int j2,int j3,int m1,int m2,int m3){
    if (m1 + m2 != m3) return 0.f;
    float pre = sqrtf((float)(2*j3+1) * f_fact(j3+j1-j2) * f_fact(j3-j1+j2) * f_fact(j1+j2-j3)
                      / f_fact(j1+j2+j3+1));
    pre *= sqrtf(f_fact(j3+m3)*f_fact(j3-m3)*f_fact(j1-m1)*f_fact(j1+m1)*f_fact(j2-m2)*f_fact(j2+m2));
    float s = 0.f;
    for (int v = 0; v <= j1 + j2 - j3; v++){
        int a1 = j1+j2-j3-v, a2 = j1-m1-v, a3 = j2+m2-v, a4 = j3-j2+m1+v, a5 = j3-j1-m2+v;
        if (a1 < 0 || a2 < 0 || a3 < 0 || a4 < 0 || a5 < 0) continue;
        float den = f_fact(v)*f_fact(a1)*f_fact(a2)*f_fact(a3)*f_fact(a4)*f_fact(a5);
        s += ((v & 1) ? -1.f : 1.f) / den;
    }
    return pre * s;
}

__device__ void u_fillf(int l, cplxf* U){
    int n = 2*l + 1;
    for (int i = 0; i < n*n; i++) U[i] = {0.f, 0.f};
    float s2 = sqrtf(0.5f);
    for (int m = -l; m <= l; m++){
        int a = l + m;
        if (m > 0){
            U[a*n + (l+m)] = {((m & 1) ? -1.f : 1.f) * s2, 0.f};
            U[a*n + (l-m)] = {s2, 0.f};
        } else if (m == 0){
            U[a*n + l] = {1.f, 0.f};
        } else {
            int mm = -m;
            U[a*n + (l+m)] = {0.f, s2};
            U[a*n + (l-m)] = {0.f, -(((mm & 1) ? -1.f : 1.f)) * s2};
        }
    }
}

// ---------------- fused prep: blocks 0..10 CG | 11 setup | 12.. weff+transpose ----------------
__global__ void __launch_bounds__(256) k_prep(const float* __restrict__ Wo0, const float* __restrict__ Wo1,
                                              const float* __restrict__ Wo2, const float* __restrict__ Wt0,
                                              const float* __restrict__ Wt1, const float* __restrict__ Wt2,
                                              const float* __restrict__ tpw, const int* __restrict__ batch,
                                              int n, int MN){
    int bid = blockIdx.x, tid = threadIdx.x;

    if (bid < NPATH){
        // ---- CG block ----
        int p = bid;
        int l1 = c_l1[p], l2 = c_l2[p], l3 = c_l3[p];
        int n1 = 2*l1+1, n2 = 2*l2+1, n3 = 2*l3+1, tot = n1*n2*n3;
        __shared__ float sCc[125];
        __shared__ cplxf sU1[25], sU2[25], sU3[25];
        __shared__ float sRe[125], sIm[125];
        __shared__ float sRed[256];

        for (int i = tid; i < tot; i += 256){
            int a = i / (n2*n3), b = (i / n3) % n2, c = i % n3;
            sCc[i] = su2_cgf(l1, l2, l3, a - l1, b - l2, c - l3);
        }
        if (tid == 0){ u_fillf(l1, sU1); u_fillf(l2, sU2); u_fillf(l3, sU3); }
        __syncthreads();

        for (int i = tid; i < tot; i += 256){
            int a = i / (n2*n3), b = (i / n3) % n2, c = i % n3;
            float re = 0, im = 0;
            for (int q1 = 0; q1 < n1; q1++)
            for (int q2 = 0; q2 < n2; q2++){
                cplxf u12 = cmulf(cconjf(sU1[a*n1 + q1]), cconjf(sU2[b*n2 + q2]));
                if (u12.re == 0.f && u12.im == 0.f) continue;
                for (int q3 = 0; q3 < n3; q3++){
                    float cc = sCc[q1*n2*n3 + q2*n3 + q3];
                    if (cc == 0.f) continue;
                    cplxf t = cmulf(u12, sU3[c*n3 + q3]);
                    re += t.re * cc; im += t.im * cc;
                }
            }
            sRe[i] = re; sIm[i] = im;
        }
        __syncthreads();

        float mr = 0.f, mi = 0.f;
        if (tid < tot){ mr = fabsf(sRe[tid]); mi = fabsf(sIm[tid]); }
        sRed[tid] = mr; __syncthreads();
        for (int s = 128; s > 0; s >>= 1){ if (tid < s) sRed[tid] = fmaxf(sRed[tid], sRed[tid+s]); __syncthreads(); }
        float maxr = sRed[0]; __syncthreads();
        sRed[tid] = mi; __syncthreads();
        for (int s = 128; s > 0; s >>= 1){ if (tid < s) sRed[tid] = fmaxf(sRed[tid], sRed[tid+s]); __syncthreads(); }
        float maxi = sRed[0]; __syncthreads();

        const float* src = (maxi > maxr) ? sIm : sRe;
        float v = (tid < tot) ? src[tid] : 0.f;
        sRed[tid] = v * v; __syncthreads();
        for (int s = 128; s > 0; s >>= 1){ if (tid < s) sRed[tid] += sRed[tid+s]; __syncthreads(); }
        float nrm = sqrtf(sRed[0]); if (nrm < 1e-12f) nrm = 1e-12f;
        if (tid < 125) g_CG[p*125 + tid] = (tid < tot) ? (v / nrm) : 0.f;

    } else if (bid == NPATH){
        // ---- setup block: batch -> slot map ----
        __shared__ int cnt[BB], starts[BB];
        if (tid < BB) cnt[tid] = 0;
        __syncthreads();
        for (int i = tid; i < n; i += 256) atomicAdd(&cnt[batch[i]], 1);
        __syncthreads();
        if (tid == 0){ int s = 0; for (int b = 0; b < BB; b++){ starts[b] = s; s += cnt[b]; } }
        __syncthreads();
        for (int i = tid; i < BB*MN; i += 256) g_nodeAt[i] = -1;
        __syncthreads();
        for (int i = tid; i < n; i += 256){
            int b = batch[i];
            int pos = i - starts[b];
            if (pos < MN) g_nodeAt[b*MN + pos] = i;
        }

    } else {
        // ---- weff + tpw transpose ----
        int idx = (bid - NPATH - 1) * 256 + tid;
        const float s0  = rsqrtf(144.f * 16.f);
        const float s12 = rsqrtf(192.f * 16.f);
        if (idx < 13824){
            int u = idx / 96, r = idx % 96, f = r >> 1, o = r & 1;
            float acc = 0.f;
            #pragma unroll
            for (int k = 0; k < 16; k++) acc += Wo0[u*768 + k*48 + f] * Wt0[k*2 + o];
            g_Weff0[idx] = acc * s0;
        } else if (idx < 23040){
            int j = idx - 13824, u = j / 48, f = j % 48;
            float acc = 0.f;
            #pragma unroll
            for (int k = 0; k < 16; k++) acc += Wo1[u*768 + k*48 + f] * Wt1[k];
            g_Weff1[j] = acc * s12;
        } else if (idx < 32256){
            int j = idx - 23040, u = j / 48, f = j % 48;
            float acc = 0.f;
            #pragma unroll
            for (int k = 0; k < 16; k++) acc += Wo2[u*768 + k*48 + f] * Wt2[k];
            g_Weff2[j] = acc * s12;
        } else if (idx < 57600){
            int j = idx - 32256, p = j / 2304, r = j % 2304, v = r / 48, u = r % 48;
            g_tpwT[p*2304 + v*48 + u] = tpw[p*2304 + u*48 + v];
        }
    }
}

// ---------------- fused per-node chain: y -> a -> o -> g -> M ----------------
__global__ void __launch_bounds__(256) k_node(const float* __restrict__ nf,
                                              const float* __restrict__ W0,
                                              const float* __restrict__ W1,
                                              const float* __restrict__ W2){
    int node = blockIdx.x, tid = threadIdx.x;
    __shared__ float s_x[432];
    __shared__ float s_y[432];
    __shared__ float s_a[1680];
    __shared__ float s_o[1680];
    __shared__ float s_g[480];

    const float sF = rsqrtf(48.f);
    const float* row = nf + (size_t)node * 432;

    // stage raw features
    for (int i = tid; i < 432; i += 256) s_x[i] = __ldg(row + i);
    __syncthreads();

    // Phase 1: y[c*48+v] = (x[c] @ W_l(c)) * sF
    for (int i = tid; i < 432; i += 256){
        int c = i / 48, v = i % 48;
        float a0 = 0.f, a1 = 0.f, a2 = 0.f, a3 = 0.f;
        if (c == 0){
            #pragma unroll
            for (int u = 0; u < 48; u += 4){
                a0 += s_x[u]   * __ldg(W0 + u*48     + v);
                a1 += s_x[u+1] * __ldg(W0 + (u+1)*48 + v);
                a2 += s_x[u+2] * __ldg(W0 + (u+2)*48 + v);
                a3 += s_x[u+3] * __ldg(W0 + (u+3)*48 + v);
            }
        } else if (c < 4){
            const int ii = c - 1;
            #pragma unroll
            for (int u = 0; u < 48; u += 4){
                a0 += s_x[48 + u*3     + ii] * __ldg(W1 + u*48     + v);
                a1 += s_x[48 + (u+1)*3 + ii] * __ldg(W1 + (u+1)*48 + v);
                a2 += s_x[48 + (u+2)*3 + ii] * __ldg(W1 + (u+2)*48 + v);
                a3 += s_x[48 + (u+3)*3 + ii] * __ldg(W1 + (u+3)*48 + v);
            }
        } else {
            const int ii = c - 4;
            #pragma unroll
            for (int u = 0; u < 48; u += 4){
                a0 += s_x[192 + u*5     + ii] * __ldg(W2 + u*48     + v);
                a1 += s_x[192 + (u+1)*5 + ii] * __ldg(W2 + (u+1)*48 + v);
                a2 += s_x[192 + (u+2)*5 + ii] * __ldg(W2 + (u+2)*48 + v);
                a3 += s_x[192 + (u+3)*5 + ii] * __ldg(W2 + (u+3)*48 + v);
            }
        }
        s_y[c*48 + v] = ((a0 + a1) + (a2 + a3)) * sF;
    }
    __syncthreads();

    // Phase 2: a[j*48+u] = (tpw[p]^T col) . y[c2]  * sF
    for (int i = tid; i < 1680; i += 256){
        int u = i % 48, j = i / 48;
        int p = c_j_p[j], c2 = c_j_c2[j];
        const float* yr = s_y + c2*48;
        const float* wT = g_tpwT + p*2304 + u;
        float a0 = 0.f, a1 = 0.f, a2 = 0.f, a3 = 0.f;
        #pragma unroll
        for (int v = 0; v < 48; v += 4){
            a0 += yr[v]   * __ldg(wT + v*48);
            a1 += yr[v+1] * __ldg(wT + (v+1)*48);
            a2 += yr[v+2] * __ldg(wT + (v+2)*48);
            a3 += yr[v+3] * __ldg(wT + (v+3)*48);
        }
        s_a[i] = ((a0 + a1) + (a2 + a3)) * sF;
    }
    __syncthreads();

    // Phase 3: CG contraction -> o (packed layout)
    for (int i = tid; i < 1680; i += 256){
        int u = i % 48, os = i / 48;
        int p = c_os_p[os], c3 = c_os_c3[os];
        int l1 = c_l1[p], l2 = c_l2[p];
        int n1 = 2*l1+1, n2 = 2*l2+1, n3 = 2*c_l3[p]+1;
        int cb1 = (l1 == 0) ? 0 : (l1 == 1) ? 1 : 4;
        int ao = c_aoff[p];
        const float* cg = g_CG + p*125 + c3;
        float acc = 0.f;
        for (int m = 0; m < n1; m++){
            float ym = s_y[(cb1 + m)*48 + u];
            for (int k = 0; k < n2; k++)
                acc += ym * s_a[(ao + k)*48 + u] * __ldg(cg + (m*n2 + k)*n3);
        }
        s_o[c_os_dst[os] + u] = acc;
    }
    __syncthreads();

    // Phase 4: g = o @ Weff
    for (int i = tid; i < 480; i += 256){
        float a0 = 0.f, a1 = 0.f, a2 = 0.f, a3 = 0.f;
        if (i < 96){
            #pragma unroll
            for (int u = 0; u < 144; u += 4){
                a0 += s_o[u]   * __ldg(g_Weff0 + u*96     + i);
                a1 += s_o[u+1] * __ldg(g_Weff0 + (u+1)*96 + i);
                a2 += s_o[u+2] * __ldg(g_Weff0 + (u+2)*96 + i);
                a3 += s_o[u+3] * __ldg(g_Weff0 + (u+3)*96 + i);
            }
            s_g[i] = (a0 + a1) + (a2 + a3);
        } else if (i < 240){
            int j = i - 96, ii = j / 48, f = j % 48;
            const float* ob = s_o + 144 + ii*192;
            #pragma unroll
            for (int u = 0; u < 192; u += 4){
                a0 += ob[u]   * __ldg(g_Weff1 + u*48     + f);
                a1 += ob[u+1] * __ldg(g_Weff1 + (u+1)*48 + f);
                a2 += ob[u+2] * __ldg(g_Weff1 + (u+2)*48 + f);
                a3 += ob[u+3] * __ldg(g_Weff1 + (u+3)*48 + f);
            }
            s_g[i] = (a0 + a1) + (a2 + a3);
        } else {
            int j = i - 240, ii = j / 48, f = j % 48;
            const float* ob = s_o + 720 + ii*192;
            #pragma unroll
            for (int u = 0; u < 192; u += 4){
                a0 += ob[u]   * __ldg(g_Weff2 + u*48     + f);
                a1 += ob[u+1] * __ldg(g_Weff2 + (u+1)*48 + f);
                a2 += ob[u+2] * __ldg(g_Weff2 + (u+2)*48 + f);
                a3 += ob[u+3] * __ldg(g_Weff2 + (u+3)*48 + f);
            }
            s_g[i] = (a0 + a1) + (a2 + a3);
        }
    }
    __syncthreads();

    // Phase 5: assemble 4x4 M per f
    if (tid < 48){
        int f = tid;
        float a0 = s_g[f*2 + 0], a1 = s_g[f*2 + 1];
        float v0 = s_g[96 + f], v1 = s_g[144 + f], v2 = s_g[192 + f];
        float dd[5];
        #pragma unroll
        for (int m = 0; m < 5; m++) dd[m] = s_g[240 + m*48 + f];
        const float* cg112 = g_CG + 5*125;   // path 5 = (1,1,2), (3,3,5)
        const float is3 = 0.57735026918962576f;
        float S[3][3];
        #pragma unroll
        for (int i = 0; i < 3; i++)
        #pragma unroll
        for (int j = 0; j < 3; j++){
            float acc = (i == j) ? a1 * is3 : 0.f;
            #pragma unroll
            for (int m = 0; m < 5; m++) acc += dd[m] * cg112[i*15 + j*5 + m];
            S[i][j] = acc;
        }
        float4* out = g_M4 + ((size_t)node*48 + f)*4;
        out[0] = make_float4(a0, v0,      v1,      v2);
        out[1] = make_float4(v0, S[0][0], S[0][1], S[0][2]);
        out[2] = make_float4(v1, S[1][0], S[1][1], S[1][2]);
        out[3] = make_float4(v2, S[2][0], S[2][1], S[2][2]);
    }
}

// ---------------- output fill (302MB) ----------------
__global__ void k_fill(float4* __restrict__ out, unsigned total4){
    unsigned idx = blockIdx.x * blockDim.x + threadIdx.x;
    if (idx >= total4) return;
    unsigned col4 = idx % 48u;
    unsigned t = idx / 48u;
    unsigned row = t % 192u;
    t = (t / 192u) >> 1;                 // strip P -> t = b*MN + pos
    int nd = g_nodeAt[t];
    float4 v = make_float4(0.f, 0.f, 0.f, 0.f);
    unsigned f = row >> 2;
    if (nd >= 0 && col4 == f)
        v = g_M4[((size_t)nd*48 + f)*4 + (row & 3u)];
    out[idx] = v;
}

// ---------------- launch ----------------
extern "C" void kernel_launch(void* const* d_in, const int* in_sizes, int n_in,
                              void* d_out, int out_size){
    const float* node_feats = (const float*)d_in[0];
    const float* W_lin0     = (const float*)d_in[1];
    const float* W_lin1     = (const float*)d_in[2];
    const float* W_lin2     = (const float*)d_in[3];
    const float* tp_w       = (const float*)d_in[4];
    const float* W_out0     = (const float*)d_in[5];
    const float* W_out1     = (const float*)d_in[6];
    const float* W_out2     = (const float*)d_in[7];
    const float* Wt0        = (const float*)d_in[8];
    const float* Wt1        = (const float*)d_in[9];
    const float* Wt2        = (const float*)d_in[10];
    const int*   batch      = (const int*)  d_in[11];

    int n  = in_sizes[0] / 432;
    int MN = out_size / (BB * PP * DD * DD);
    unsigned total4 = (unsigned)(out_size / 4);

    // prep grid: 11 CG blocks + 1 setup block + ceil(57600/256)=225 weff blocks
    k_prep<<<NPATH + 1 + 225, 256>>>(W_out0, W_out1, W_out2, Wt0, Wt1, Wt2, tp_w, batch, n, MN);
    k_node<<<n, 256>>>(node_feats, W_lin0, W_lin1, W_lin2);
    k_fill<<<(total4 + 255)/256, 256>>>((float4*)d_out, total4);
}